// round 16
// baseline (speedup 1.0000x reference)
#include <cuda_runtime.h>
#include <cstdint>

#define KQW      50
#define NCH      128          // key/value channels
#define NBINS    4096
#define CAND_CAP 32768
#define FCAP     2048         // filtered candidates in epilogue
#define MAXN     1048576
#define NB_DIST  912          // 152 SMs * 6 blocks
#define NCOMP    64           // compactor blocks (last 64 arrivers)

// ---- scratch (device globals, zero at module load; kernel self-cleans) ----
__device__ float    g_w[MAXN];          // per-row weights (4 MB)
__device__ float    g_bsum[NB_DIST];    // per-block partial sums of weights
__device__ unsigned g_hist[NBINS];      // coarse histogram (bits >> 19)
__device__ float    g_wsum;             // total weight sum
__device__ unsigned g_thresh_bin;       // boundary coarse bin b*
__device__ unsigned g_above;            // count strictly above b* (< 50)
__device__ unsigned g_done;             // arrival counter (stream phase)
__device__ unsigned g_done2;            // arrival counter (compact phase)
__device__ unsigned g_flag;             // threshold-ready flag
__device__ unsigned g_ncand;            // candidate counter
__device__ int      g_cand[CAND_CAP];   // candidate row indices
__device__ unsigned g_cwb[CAND_CAP];    // candidate weight bits

__device__ __forceinline__ unsigned coarse_bin(unsigned u) { return u >> 19; }
__device__ __forceinline__ unsigned sub_bin(unsigned u)    { return (u >> 7) & 0xFFFu; }

// smem overlay: coarse/sub histogram vs filtered candidate arrays.
// h is dead before f is written (separated by __syncthreads).
union SmemU {
    unsigned h[NBINS];                       // 16 KB
    struct { float fw[FCAP]; int fi[FCAP]; } f;   // 8 + 8 KB
};

// ------------------------------------------------------------------
// Parallel boundary-bin search over a 4096-bin histogram in smem.
// Smallest bin b* with suffix-count >= need. One thread writes out.
// ------------------------------------------------------------------
__device__ __forceinline__ void find_boundary(
    const unsigned* __restrict__ h, unsigned need,
    unsigned* csum, unsigned* suf,
    unsigned* out_bin, unsigned* out_above)
{
    const int tid = threadIdx.x;
    unsigned s = 0u;
    const int base = tid * (NBINS / 256);
    #pragma unroll
    for (int i = 0; i < NBINS / 256; i++) s += h[base + i];
    csum[tid] = s;
    suf[tid]  = s;
    __syncthreads();
    #pragma unroll
    for (int o = 1; o < 256; o <<= 1) {
        unsigned v = suf[tid];
        unsigned add = (tid + o < 256) ? suf[tid + o] : 0u;
        __syncthreads();
        suf[tid] = v + add;
        __syncthreads();
    }
    unsigned above_chunks = (tid + 1 < 256) ? suf[tid + 1] : 0u;
    if (above_chunks < need && suf[tid] >= need) {
        unsigned cum = above_chunks;
        int b = base + (NBINS / 256) - 1;
        for (;; b--) {
            if (b <= base) break;
            if (cum + h[b] >= need) break;
            cum += h[b];
        }
        *out_bin = (unsigned)b;
        *out_above = cum;
    }
}

// ------------------------------------------------------------------
// Single persistent kernel:
//   Phase A: 512MB stream (R11 loop: warp-strided, 48 warps/SM,
//            6-SHFL butterfly reduce), histogram, block sums.
//   Phase B: last arriver computes wsum + coarse threshold, raises
//            flag; last-64 arrivers spin (deadlock-safe: spinners are
//            executing by construction), then compact their slice.
//   Phase C: last compactor runs refine + exact top-50 + gather.
// ------------------------------------------------------------------
__global__ void __launch_bounds__(256, 6)
k_all(const float* __restrict__ key, const float* __restrict__ keys,
      const float* __restrict__ values, float* __restrict__ out,
      int n, int n4) {
    __shared__ SmemU    u;
    __shared__ float    ssum[8];
    __shared__ unsigned csum[256];
    __shared__ unsigned suf[256];
    __shared__ float    ss[256];
    __shared__ unsigned s_pos, s_sbin, s_m;
    __shared__ float    sel_w[KQW];
    __shared__ int      sel_i[KQW];
    __shared__ float    part[2 * NCH];

    const int tid = threadIdx.x;
    for (int i = tid; i < NBINS; i += 256) u.h[i] = 0u;
    __syncthreads();

    const int lane  = tid & 31;
    const int wid   = tid >> 5;
    const int gwarp = (blockIdx.x * 256 + tid) >> 5;
    const int nwarp = (gridDim.x * 256) >> 5;
    const unsigned G = gridDim.x;

    const float4* kp = reinterpret_cast<const float4*>(keys);
    const float4  kq = reinterpret_cast<const float4*>(key)[lane];

    const unsigned FULL = 0xffffffffu;
    const bool hi16 = (lane & 16) != 0;
    const bool hi8  = (lane & 8)  != 0;
    const int  g    = lane >> 3;
    const int  goff = ((g & 1) << 1) | (g >> 1);   // perm {0,2,1,3}

    float lsum = 0.f;
    int row = gwarp;

    // ---------------- Phase A: stream ----------------
    for (; row + 3 * nwarp < n; row += 4 * nwarp) {
        float4 a0 = __ldcs(&kp[(size_t)row * 32 + lane]);
        float4 a1 = __ldcs(&kp[(size_t)(row +     nwarp) * 32 + lane]);
        float4 a2 = __ldcs(&kp[(size_t)(row + 2 * nwarp) * 32 + lane]);
        float4 a3 = __ldcs(&kp[(size_t)(row + 3 * nwarp) * 32 + lane]);

        float dx, dy, dz, dw;
        dx = kq.x - a0.x; dy = kq.y - a0.y; dz = kq.z - a0.z; dw = kq.w - a0.w;
        float s0 = dx*dx + dy*dy + dz*dz + dw*dw;
        dx = kq.x - a1.x; dy = kq.y - a1.y; dz = kq.z - a1.z; dw = kq.w - a1.w;
        float s1 = dx*dx + dy*dy + dz*dz + dw*dw;
        dx = kq.x - a2.x; dy = kq.y - a2.y; dz = kq.z - a2.z; dw = kq.w - a2.w;
        float s2 = dx*dx + dy*dy + dz*dz + dw*dw;
        dx = kq.x - a3.x; dy = kq.y - a3.y; dz = kq.z - a3.z; dw = kq.w - a3.w;
        float s3 = dx*dx + dy*dy + dz*dz + dw*dw;

        // butterfly stage 1 (xor 16): merge rows {0,1} and {2,3}
        float p01 = hi16 ? s1 : s0;
        float q01 = hi16 ? s0 : s1;
        p01 += __shfl_xor_sync(FULL, q01, 16);
        float p23 = hi16 ? s3 : s2;
        float q23 = hi16 ? s2 : s3;
        p23 += __shfl_xor_sync(FULL, q23, 16);
        // stage 2 (xor 8)
        float p = hi8 ? p23 : p01;
        float q = hi8 ? p01 : p23;
        p += __shfl_xor_sync(FULL, q, 8);
        // final 3 levels
        p += __shfl_xor_sync(FULL, p, 4);
        p += __shfl_xor_sync(FULL, p, 2);
        p += __shfl_xor_sync(FULL, p, 1);

        if ((lane & 7) == 0) {
            float wv = 1.f / (p + 1e-3f);
            g_w[row + goff * nwarp] = wv;
            atomicAdd(&u.h[__float_as_uint(wv) >> 19], 1u);
            lsum += wv;
        }
    }
    for (; row < n; row += nwarp) {
        float4 a = __ldcs(&kp[(size_t)row * 32 + lane]);
        float dx = kq.x - a.x, dy = kq.y - a.y, dz = kq.z - a.z, dw = kq.w - a.w;
        float s0 = dx*dx + dy*dy + dz*dz + dw*dw;
        #pragma unroll
        for (int o = 16; o; o >>= 1) s0 += __shfl_xor_sync(FULL, s0, o);
        if (lane == 0) {
            float wv = 1.f / (s0 + 1e-3f);
            g_w[row] = wv;
            lsum += wv;
            atomicAdd(&u.h[__float_as_uint(wv) >> 19], 1u);
        }
    }

    // deterministic block-level weight sum + histogram merge
    #pragma unroll
    for (int o = 16; o; o >>= 1) lsum += __shfl_xor_sync(FULL, lsum, o);
    if (lane == 0) ssum[wid] = lsum;
    __syncthreads();
    if (tid == 0) {
        float t = 0.f;
        for (int i = 0; i < 8; i++) t += ssum[i];
        g_bsum[blockIdx.x] = t;
    }
    for (int i = tid; i < NBINS; i += 256) {
        unsigned cnt = u.h[i];
        if (cnt) atomicAdd(&g_hist[i], cnt);
    }

    // ---------------- arrival ----------------
    __threadfence();
    __syncthreads();
    if (tid == 0) s_pos = atomicAdd(&g_done, 1u);
    __syncthreads();
    const unsigned pos = s_pos;
    if (pos < G - NCOMP) return;          // early blocks exit (SM idles anyway)

    if (pos == G - 1u) {
        // ---- threshold epilogue (all writes visible: everyone fenced) ----
        for (int i = tid; i < NBINS; i += 256) u.h[i] = g_hist[i];
        float t = 0.f;
        for (int i = tid; i < (int)G; i += 256) t += g_bsum[i];
        ss[tid] = t;
        __syncthreads();
        for (int o = 128; o; o >>= 1) {
            if (tid < o) ss[tid] += ss[tid + o];
            __syncthreads();
        }
        if (tid == 0) g_wsum = ss[0];
        find_boundary(u.h, (unsigned)KQW, csum, suf, &g_thresh_bin, &g_above);
        for (int i = tid; i < NBINS; i += 256) g_hist[i] = 0u;  // clean for replay
        __threadfence();
        __syncthreads();
        if (tid == 0) atomicExch(&g_flag, 1u);
    } else {
        // deadlock-safe spin: this block IS executing; the flag setter
        // is the final arriver, which is also executing.
        if (tid == 0) {
            while (atomicAdd(&g_flag, 0u) == 0u) __nanosleep(64);
        }
        __syncthreads();
        __threadfence();   // acquire threshold/g_w visibility
    }

    // ---------------- Phase B: compaction (NCOMP blocks) ----------------
    const int r = (int)(pos - (G - NCOMP));          // 0..NCOMP-1
    const unsigned tb = g_thresh_bin;
    const float4* w4 = reinterpret_cast<const float4*>(g_w);
    const int lo = (int)(((long long)n4 * r) / NCOMP);
    const int hi = (int)(((long long)n4 * (r + 1)) / NCOMP);

    for (int i = lo + tid; i < hi; i += 256) {
        float4 v = w4[i];
        unsigned uu[4] = { __float_as_uint(v.x), __float_as_uint(v.y),
                           __float_as_uint(v.z), __float_as_uint(v.w) };
        #pragma unroll
        for (int c = 0; c < 4; c++) {
            if (coarse_bin(uu[c]) >= tb) {
                unsigned p = atomicAdd(&g_ncand, 1u);
                if (p < CAND_CAP) { g_cand[p] = 4 * i + c; g_cwb[p] = uu[c]; }
            }
        }
    }
    if (r == 0 && tid == 0) {
        for (int i = n4 * 4; i < n; i++) {
            unsigned uu = __float_as_uint(g_w[i]);
            if (coarse_bin(uu) >= tb) {
                unsigned p = atomicAdd(&g_ncand, 1u);
                if (p < CAND_CAP) { g_cand[p] = i; g_cwb[p] = uu; }
            }
        }
    }

    __threadfence();
    __syncthreads();
    if (tid == 0) s_pos = atomicAdd(&g_done2, 1u);
    __syncthreads();
    if (s_pos != (unsigned)(NCOMP - 1)) return;

    // ---------------- Phase C: refine + top-50 + gather (1 block) -------
    int nc = (int)min(g_ncand, (unsigned)CAND_CAP);

    for (int i = tid; i < NBINS; i += 256) u.h[i] = 0u;
    if (tid == 0) s_m = 0u;
    __syncthreads();

    // histogram of boundary-bin candidates by sub-bits
    for (int i = tid; i < nc; i += 256) {
        unsigned uu = g_cwb[i];
        if (coarse_bin(uu) == tb) atomicAdd(&u.h[sub_bin(uu)], 1u);
    }
    __syncthreads();

    const unsigned need = (unsigned)KQW - g_above;   // 1..50
    unsigned dummy;
    find_boundary(u.h, need, csum, suf, &s_sbin, &dummy);
    __syncthreads();
    const unsigned sb = s_sbin;
    __syncthreads();          // u.h dead from here; u.f overlays it

    // filter candidates into shared (overlay)
    for (int i = tid; i < nc; i += 256) {
        unsigned uu = g_cwb[i];
        if (coarse_bin(uu) > tb || sub_bin(uu) >= sb) {
            unsigned p = atomicAdd(&s_m, 1u);
            if (p < FCAP) { u.f.fw[p] = __uint_as_float(uu); u.f.fi[p] = g_cand[i]; }
        }
    }
    for (int i = tid; i < KQW; i += 256) { sel_w[i] = 0.f; sel_i[i] = 0; }
    __syncthreads();

    int m = (int)min(s_m, (unsigned)FCAP);

    // exact top-50 by rank counting (value desc, index asc tiebreak)
    for (int i = tid; i < m; i += 256) {
        const float wi = u.f.fw[i];
        const int   ii = u.f.fi[i];
        int rank = 0;
        for (int j = 0; j < m; j++) {
            float wj = u.f.fw[j];
            rank += (wj > wi) || (wj == wi && u.f.fi[j] < ii);
        }
        if (rank < KQW) { sel_w[rank] = wi; sel_i[rank] = ii; }
    }
    __syncthreads();

    const int ns = m < KQW ? m : KQW;
    const int ch = tid & (NCH - 1);
    const int tm = tid >> 7;    // two teams over selections
    float a0 = 0.f, a1 = 0.f, a2 = 0.f, a3 = 0.f;
    int j = tm;
    for (; j + 6 < ns; j += 8) {
        a0 += sel_w[j]     * __ldg(&values[(size_t)sel_i[j]     * NCH + ch]);
        a1 += sel_w[j + 2] * __ldg(&values[(size_t)sel_i[j + 2] * NCH + ch]);
        a2 += sel_w[j + 4] * __ldg(&values[(size_t)sel_i[j + 4] * NCH + ch]);
        a3 += sel_w[j + 6] * __ldg(&values[(size_t)sel_i[j + 6] * NCH + ch]);
    }
    for (; j < ns; j += 2)
        a0 += sel_w[j] * __ldg(&values[(size_t)sel_i[j] * NCH + ch]);
    part[tm * NCH + ch] = ((a0 + a1) + (a2 + a3));
    __syncthreads();
    if (tid < NCH)
        out[tid] = (part[tid] + part[NCH + tid]) / g_wsum;

    // reset counters for the next graph replay
    if (tid == 0) {
        g_done  = 0u;
        g_done2 = 0u;
        g_flag  = 0u;
        g_ncand = 0u;
    }
}

// ------------------------------------------------------------------
extern "C" void kernel_launch(void* const* d_in, const int* in_sizes, int n_in,
                              void* d_out, int out_size) {
    const float* key    = (const float*)d_in[0];
    const float* keys   = (const float*)d_in[1];
    const float* values = (const float*)d_in[2];
    float* out = (float*)d_out;

    const int n = in_sizes[1] / NCH;   // number of memory rows (1,000,000)

    k_all<<<NB_DIST, 256>>>(key, keys, values, out, n, n / 4);
}

// round 17
// speedup vs baseline: 1.0664x; 1.0664x over previous
#include <cuda_runtime.h>
#include <cstdint>

#define KQW      50
#define NCH      128          // key/value channels
#define NBINS    4096
#define CAND_CAP 32768
#define FCAP     2048         // filtered candidates in k_final
#define MAXN     1048576
#define NB_DIST  912          // 152 SMs * 6 blocks
#define NWARP    (NB_DIST * 8)
#define REMCAP   (4 * NWARP)

// ---- scratch (device globals, zero at module load; kernels self-clean) ----
__device__ float    g_wp[MAXN];          // permuted weights, coalesced 16B/warp
__device__ float    g_wrem[REMCAP];      // remainder-row weights (by row - rs)
__device__ float    g_bsum[NB_DIST];     // per-block partial sums of weights
__device__ unsigned g_hist[NBINS];       // coarse histogram (bits >> 19)
__device__ float    g_wsum;              // total weight sum
__device__ unsigned g_thresh_bin;        // boundary coarse bin b*
__device__ unsigned g_above;             // count strictly above b* (< 50)
__device__ unsigned g_done;              // k_dist completion counter
__device__ unsigned g_ncand;             // candidate counter
__device__ int      g_cand[CAND_CAP];    // candidate row indices
__device__ unsigned g_cwb[CAND_CAP];     // candidate weight bits

__device__ __forceinline__ unsigned coarse_bin(unsigned u) { return u >> 19; }
__device__ __forceinline__ unsigned sub_bin(unsigned u)    { return (u >> 7) & 0xFFFu; }

// ------------------------------------------------------------------
// Parallel boundary-bin search over a 4096-bin histogram in smem.
// ------------------------------------------------------------------
__device__ __forceinline__ void find_boundary(
    const unsigned* __restrict__ h, unsigned need,
    unsigned* csum, unsigned* suf,
    unsigned* out_bin, unsigned* out_above)
{
    const int tid = threadIdx.x;
    unsigned s = 0u;
    const int base = tid * (NBINS / 256);
    #pragma unroll
    for (int i = 0; i < NBINS / 256; i++) s += h[base + i];
    csum[tid] = s;
    suf[tid]  = s;
    __syncthreads();
    #pragma unroll
    for (int o = 1; o < 256; o <<= 1) {
        unsigned v = suf[tid];
        unsigned add = (tid + o < 256) ? suf[tid + o] : 0u;
        __syncthreads();
        suf[tid] = v + add;
        __syncthreads();
    }
    unsigned above_chunks = (tid + 1 < 256) ? suf[tid + 1] : 0u;
    if (above_chunks < need && suf[tid] >= need) {
        unsigned cum = above_chunks;
        int b = base + (NBINS / 256) - 1;
        for (;; b--) {
            if (b <= base) break;
            if (cum + h[b] >= need) break;
            cum += h[b];
        }
        *out_bin = (unsigned)b;
        *out_above = cum;
    }
}

// ------------------------------------------------------------------
// K1: 512MB streaming pass (warp-strided schedule, uniform IT),
// 6-SHFL butterfly reduce; lane 0 gathers 4 group sums and stores
// ONE float4 to g_wp (coalesced across adjacent warps).
// Fused threshold via last-block-done.
// g_wp[(i*NWARP+gw)*4 + g] = weight of row gw + (4i + perm[g])*NWARP,
// perm = {0, 2, 1, 3}.
// ------------------------------------------------------------------
__global__ void __launch_bounds__(256, 6)
k_dist(const float* __restrict__ key, const float* __restrict__ keys,
       int n, int IT) {
    __shared__ unsigned hist[NBINS];
    __shared__ float    ssum[8];
    __shared__ unsigned s_last;
    for (int i = threadIdx.x; i < NBINS; i += 256) hist[i] = 0u;
    __syncthreads();

    const int lane  = threadIdx.x & 31;
    const int wid   = threadIdx.x >> 5;
    const int gwarp = (blockIdx.x * 256 + threadIdx.x) >> 5;
    const int nwarp = NWARP;

    const float4* kp = reinterpret_cast<const float4*>(keys);
    const float4  kq = reinterpret_cast<const float4*>(key)[lane];

    const unsigned FULL = 0xffffffffu;
    const bool hi16 = (lane & 16) != 0;
    const bool hi8  = (lane & 8)  != 0;

    float lsum = 0.f;
    int row = gwarp;

    for (int i = 0; i < IT; i++, row += 4 * nwarp) {
        float4 a0 = __ldcs(&kp[(size_t)row * 32 + lane]);
        float4 a1 = __ldcs(&kp[(size_t)(row +     nwarp) * 32 + lane]);
        float4 a2 = __ldcs(&kp[(size_t)(row + 2 * nwarp) * 32 + lane]);
        float4 a3 = __ldcs(&kp[(size_t)(row + 3 * nwarp) * 32 + lane]);

        float dx, dy, dz, dw;
        dx = kq.x - a0.x; dy = kq.y - a0.y; dz = kq.z - a0.z; dw = kq.w - a0.w;
        float s0 = dx*dx + dy*dy + dz*dz + dw*dw;
        dx = kq.x - a1.x; dy = kq.y - a1.y; dz = kq.z - a1.z; dw = kq.w - a1.w;
        float s1 = dx*dx + dy*dy + dz*dz + dw*dw;
        dx = kq.x - a2.x; dy = kq.y - a2.y; dz = kq.z - a2.z; dw = kq.w - a2.w;
        float s2 = dx*dx + dy*dy + dz*dz + dw*dw;
        dx = kq.x - a3.x; dy = kq.y - a3.y; dz = kq.z - a3.z; dw = kq.w - a3.w;
        float s3 = dx*dx + dy*dy + dz*dz + dw*dw;

        // butterfly: stage 1 (xor 16) merges {0,1} and {2,3}
        float p01 = hi16 ? s1 : s0;
        float q01 = hi16 ? s0 : s1;
        p01 += __shfl_xor_sync(FULL, q01, 16);
        float p23 = hi16 ? s3 : s2;
        float q23 = hi16 ? s2 : s3;
        p23 += __shfl_xor_sync(FULL, q23, 16);
        // stage 2 (xor 8)
        float p = hi8 ? p23 : p01;
        float q = hi8 ? p01 : p23;
        p += __shfl_xor_sync(FULL, q, 8);
        // final 3 levels
        p += __shfl_xor_sync(FULL, p, 4);
        p += __shfl_xor_sync(FULL, p, 2);
        p += __shfl_xor_sync(FULL, p, 1);

        float wv = 1.f / (p + 1e-3f);          // valid on all lanes
        if ((lane & 7) == 0) {
            atomicAdd(&hist[__float_as_uint(wv) >> 19], 1u);
            lsum += wv;
        }
        // gather the 4 group weights into lane 0 and store one float4
        float w1 = __shfl_sync(FULL, wv, 8);
        float w2 = __shfl_sync(FULL, wv, 16);
        float w3 = __shfl_sync(FULL, wv, 24);
        if (lane == 0) {
            float4 o; o.x = wv; o.y = w1; o.z = w2; o.w = w3;
            reinterpret_cast<float4*>(g_wp)[(size_t)i * nwarp + gwarp] = o;
        }
    }
    // remainder rows [IT*4*nwarp, n)
    const int rs = IT * 4 * nwarp;
    for (row = rs + gwarp; row < n; row += nwarp) {
        float4 a = __ldcs(&kp[(size_t)row * 32 + lane]);
        float dx = kq.x - a.x, dy = kq.y - a.y, dz = kq.z - a.z, dw = kq.w - a.w;
        float s0 = dx*dx + dy*dy + dz*dz + dw*dw;
        #pragma unroll
        for (int o = 16; o; o >>= 1) s0 += __shfl_xor_sync(FULL, s0, o);
        if (lane == 0) {
            float wv = 1.f / (s0 + 1e-3f);
            g_wrem[row - rs] = wv;
            lsum += wv;
            atomicAdd(&hist[__float_as_uint(wv) >> 19], 1u);
        }
    }

    // deterministic block-level weight sum
    #pragma unroll
    for (int o = 16; o; o >>= 1) lsum += __shfl_xor_sync(FULL, lsum, o);
    if (lane == 0) ssum[wid] = lsum;
    __syncthreads();
    if (threadIdx.x == 0) {
        float t = 0.f;
        for (int i = 0; i < 8; i++) t += ssum[i];
        g_bsum[blockIdx.x] = t;
    }
    for (int i = threadIdx.x; i < NBINS; i += 256) {
        unsigned cnt = hist[i];
        if (cnt) atomicAdd(&g_hist[i], cnt);
    }

    // ---- last-block-done: fused threshold computation ----
    __threadfence();
    __syncthreads();
    if (threadIdx.x == 0)
        s_last = (atomicAdd(&g_done, 1u) == gridDim.x - 1u) ? 1u : 0u;
    __syncthreads();
    if (!s_last) return;

    __shared__ unsigned csum[256];
    __shared__ unsigned suf[256];
    __shared__ float    ss[256];
    const int tid = threadIdx.x;

    for (int i = tid; i < NBINS; i += 256) hist[i] = g_hist[i];

    float t = 0.f;
    for (int i = tid; i < (int)gridDim.x; i += 256) t += g_bsum[i];
    ss[tid] = t;
    __syncthreads();
    for (int o = 128; o; o >>= 1) {
        if (tid < o) ss[tid] += ss[tid + o];
        __syncthreads();
    }
    if (tid == 0) { g_wsum = ss[0]; g_done = 0u; }

    find_boundary(hist, (unsigned)KQW, csum, suf, &g_thresh_bin, &g_above);

    for (int i = tid; i < NBINS; i += 256) g_hist[i] = 0u;   // clean for replay
}

// ------------------------------------------------------------------
// K2: loose compaction over the permuted weight array (float4 scan,
// coalesced) + small remainder. Maps permuted index -> row.
// ------------------------------------------------------------------
__global__ void __launch_bounds__(256)
k_compact(int n, int IT) {
    const int gid = blockIdx.x * 256 + threadIdx.x;
    const unsigned tb = g_thresh_bin;
    const int nwarp = NWARP;
    const int nq = IT * nwarp;              // number of float4 entries
    const int stride = gridDim.x * 256;
    const int perm[4] = {0, 2, 1, 3};

    const float4* wp4 = reinterpret_cast<const float4*>(g_wp);
    for (int q = gid; q < nq; q += stride) {
        float4 v = wp4[q];
        unsigned u[4] = { __float_as_uint(v.x), __float_as_uint(v.y),
                          __float_as_uint(v.z), __float_as_uint(v.w) };
        unsigned hit = (coarse_bin(u[0]) >= tb) | (coarse_bin(u[1]) >= tb) |
                       (coarse_bin(u[2]) >= tb) | (coarse_bin(u[3]) >= tb);
        if (hit) {
            const int i  = q / nwarp;
            const int gw = q - i * nwarp;
            #pragma unroll
            for (int g = 0; g < 4; g++) {
                if (coarse_bin(u[g]) >= tb) {
                    const int row = gw + (4 * i + perm[g]) * nwarp;
                    unsigned p = atomicAdd(&g_ncand, 1u);
                    if (p < CAND_CAP) { g_cand[p] = row; g_cwb[p] = u[g]; }
                }
            }
        }
    }
    // remainder rows
    const int rs = IT * 4 * nwarp;
    for (int r = gid; r < n - rs; r += stride) {
        unsigned u = __float_as_uint(g_wrem[r]);
        if (coarse_bin(u) >= tb) {
            unsigned p = atomicAdd(&g_ncand, 1u);
            if (p < CAND_CAP) { g_cand[p] = rs + r; g_cwb[p] = u; }
        }
    }
}

// ------------------------------------------------------------------
// K3 (1 block): in-block radix refine on candidates (sub-bits 7..18),
// filter to ~50-100, exact top-50 rank count (value desc, index asc —
// jax.lax.top_k tiebreak), gather + weighted sum. Resets g_ncand.
// ------------------------------------------------------------------
__global__ void __launch_bounds__(256)
k_final(const float* __restrict__ values, float* __restrict__ out) {
    __shared__ unsigned h[NBINS];
    __shared__ unsigned csum[256];
    __shared__ unsigned suf[256];
    __shared__ unsigned s_sbin, s_m;
    __shared__ float fw[FCAP];
    __shared__ int   fi[FCAP];
    __shared__ float sel_w[KQW];
    __shared__ int   sel_i[KQW];
    __shared__ float part[2 * NCH];

    const int tid = threadIdx.x;
    const unsigned tb = g_thresh_bin;
    int nc = (int)min(g_ncand, (unsigned)CAND_CAP);

    for (int i = tid; i < NBINS; i += 256) h[i] = 0u;
    if (tid == 0) { s_m = 0u; }
    __syncthreads();
    if (tid == 0) g_ncand = 0u;   // clean for next replay

    for (int i = tid; i < nc; i += 256) {
        unsigned u = g_cwb[i];
        if (coarse_bin(u) == tb) atomicAdd(&h[sub_bin(u)], 1u);
    }
    __syncthreads();

    const unsigned need = (unsigned)KQW - g_above;   // 1..50
    unsigned dummy;
    find_boundary(h, need, csum, suf, &s_sbin, &dummy);
    __syncthreads();
    const unsigned sb = s_sbin;

    for (int i = tid; i < nc; i += 256) {
        unsigned u = g_cwb[i];
        if (coarse_bin(u) > tb || sub_bin(u) >= sb) {
            unsigned p = atomicAdd(&s_m, 1u);
            if (p < FCAP) { fw[p] = __uint_as_float(u); fi[p] = g_cand[i]; }
        }
    }
    for (int i = tid; i < KQW; i += 256) { sel_w[i] = 0.f; sel_i[i] = 0; }
    __syncthreads();

    int m = (int)min(s_m, (unsigned)FCAP);

    for (int i = tid; i < m; i += 256) {
        const float wi = fw[i];
        const int   ii = fi[i];
        int rank = 0;
        for (int j = 0; j < m; j++) {
            float wj = fw[j];
            rank += (wj > wi) || (wj == wi && fi[j] < ii);
        }
        if (rank < KQW) { sel_w[rank] = wi; sel_i[rank] = ii; }
    }
    __syncthreads();

    const int ns = m < KQW ? m : KQW;
    const int ch = tid & (NCH - 1);
    const int tm = tid >> 7;    // two teams over selections
    float a0 = 0.f, a1 = 0.f, a2 = 0.f, a3 = 0.f;
    int j = tm;
    for (; j + 6 < ns; j += 8) {
        a0 += sel_w[j]     * __ldg(&values[(size_t)sel_i[j]     * NCH + ch]);
        a1 += sel_w[j + 2] * __ldg(&values[(size_t)sel_i[j + 2] * NCH + ch]);
        a2 += sel_w[j + 4] * __ldg(&values[(size_t)sel_i[j + 4] * NCH + ch]);
        a3 += sel_w[j + 6] * __ldg(&values[(size_t)sel_i[j + 6] * NCH + ch]);
    }
    for (; j < ns; j += 2)
        a0 += sel_w[j] * __ldg(&values[(size_t)sel_i[j] * NCH + ch]);
    part[tm * NCH + ch] = ((a0 + a1) + (a2 + a3));
    __syncthreads();
    if (tid < NCH)
        out[tid] = (part[tid] + part[NCH + tid]) / g_wsum;
}

// ------------------------------------------------------------------
extern "C" void kernel_launch(void* const* d_in, const int* in_sizes, int n_in,
                              void* d_out, int out_size) {
    const float* key    = (const float*)d_in[0];
    const float* keys   = (const float*)d_in[1];
    const float* values = (const float*)d_in[2];
    float* out = (float*)d_out;

    const int n  = in_sizes[1] / NCH;        // number of memory rows
    const int IT = n / (4 * NWARP);          // uniform main-loop iterations

    k_dist   <<<NB_DIST, 256>>>(key, keys, n, IT);
    k_compact<<<1024, 256>>>(n, IT);
    k_final  <<<1, 256>>>(values, out);
}